// round 1
// baseline (speedup 1.0000x reference)
#include <cuda_runtime.h>
#include <math.h>

#define BB 4
#define SS 2048
#define DD 512
#define HH 8
#define DH 64   // DK == DV == 64

// ---------------- scratch (allocation-free: __device__ globals) ----------------
__device__ float g_q[BB * HH * SS * DH];    // (B,H,S,64)
__device__ float g_k[BB * HH * SS * DH];
__device__ float g_v[BB * HH * SS * DH];
__device__ float g_ctx[BB * SS * HH * DH];  // (B,S,512)

// ---------------- generic tiled SGEMM: C = A[M,K] @ W[K,N] + bias[N] ----------------
// BM=BN=64, BK=16, 256 threads, 4x4 micro-tile.
// SPLIT=true: write C into split-head layout (B,H,S,64) assuming N=512, S=2048, H=8.
template <bool SPLIT>
__global__ __launch_bounds__(256) void gemm_kernel(
    const float* __restrict__ A, const float* __restrict__ W,
    const float* __restrict__ bias, float* __restrict__ C,
    int M, int K, int N)
{
    __shared__ float As[16][64];  // k-major (transposed A tile)
    __shared__ float Ws[16][64];

    const int tid = threadIdx.x;
    const int tx = tid & 15;      // n group
    const int ty = tid >> 4;      // m group
    const int m0 = blockIdx.y * 64;
    const int n0 = blockIdx.x * 64;

    const int arow = tid >> 2, aseg = tid & 3;   // A tile load: 64 rows x 4 float4
    const int wrow = tid >> 4, wseg = tid & 15;  // W tile load: 16 rows x 16 float4

    float acc[4][4];
#pragma unroll
    for (int i = 0; i < 4; i++)
#pragma unroll
        for (int j = 0; j < 4; j++) acc[i][j] = 0.0f;

    for (int k0 = 0; k0 < K; k0 += 16) {
        float4 a4 = *reinterpret_cast<const float4*>(
            &A[(size_t)(m0 + arow) * K + k0 + aseg * 4]);
        As[aseg * 4 + 0][arow] = a4.x;
        As[aseg * 4 + 1][arow] = a4.y;
        As[aseg * 4 + 2][arow] = a4.z;
        As[aseg * 4 + 3][arow] = a4.w;
        float4 w4 = *reinterpret_cast<const float4*>(
            &W[(size_t)(k0 + wrow) * N + n0 + wseg * 4]);
        *reinterpret_cast<float4*>(&Ws[wrow][wseg * 4]) = w4;
        __syncthreads();

#pragma unroll
        for (int k = 0; k < 16; k++) {
            float4 av = *reinterpret_cast<const float4*>(&As[k][ty * 4]);
            float4 wv = *reinterpret_cast<const float4*>(&Ws[k][tx * 4]);
            float a[4] = {av.x, av.y, av.z, av.w};
            float w[4] = {wv.x, wv.y, wv.z, wv.w};
#pragma unroll
            for (int i = 0; i < 4; i++)
#pragma unroll
                for (int j = 0; j < 4; j++) acc[i][j] += a[i] * w[j];
        }
        __syncthreads();
    }

#pragma unroll
    for (int i = 0; i < 4; i++) {
        const int m = m0 + ty * 4 + i;
#pragma unroll
        for (int j = 0; j < 4; j++) {
            const int n = n0 + tx * 4 + j;
            const float v = acc[i][j] + bias[n];
            if (SPLIT) {
                const int b = m >> 11;      // / 2048
                const int s = m & 2047;
                const int h = n >> 6;
                const int d = n & 63;
                C[(((size_t)(b * HH + h)) * SS + s) * 64 + d] = v;
            } else {
                C[(size_t)m * N + n] = v;
            }
        }
    }
}

// ---------------- flash-attention kernel ----------------
// grid: (S/64, B*H), 256 threads. Tiles: 64 queries x 64 keys, dh=64.
// Reproduces the reference's fp32 mask-absorption semantics by adding the
// +-1e9 additive masks in fp32 (key-axis then query-axis, like the reference).
__global__ __launch_bounds__(256) void attn_kernel(
    const float* __restrict__ Q, const float* __restrict__ K,
    const float* __restrict__ V, const int* __restrict__ mask,
    float* __restrict__ ctx)
{
    extern __shared__ float sm[];
    float(*Qt)[68] = reinterpret_cast<float(*)[68]>(sm);             // Qt[d][r]
    float(*Kt)[68] = reinterpret_cast<float(*)[68]>(sm + 64 * 68);   // Kt[d][c]
    float(*Vs)[68] = reinterpret_cast<float(*)[68]>(sm + 2 * 64 * 68);  // Vs[k][d]
    float(*Ps)[68] = reinterpret_cast<float(*)[68]>(sm + 3 * 64 * 68);  // Ps[r][k]
    float* Mk = sm + 4 * 64 * 68;  // [64] key-mask additive values

    const int tid = threadIdx.x;
    const int tc = tid & 15;   // col group (keys in QK, dims in PV)
    const int tr = tid >> 4;   // row group (queries)
    const int bh = blockIdx.y;
    const int b = bh >> 3;     // H = 8
    const int h = bh & 7;
    const int q0 = blockIdx.x * 64;

    const float* Qb = Q + (size_t)bh * (SS * 64);
    const float* Kb = K + (size_t)bh * (SS * 64);
    const float* Vb = V + (size_t)bh * (SS * 64);
    const int* mrow = mask + b * SS;

    // load Q tile transposed (d-major)
    {
        const int row = tid >> 2, seg = tid & 3;
        const float4* src =
            reinterpret_cast<const float4*>(&Qb[(size_t)(q0 + row) * 64 + seg * 16]);
#pragma unroll
        for (int i = 0; i < 4; i++) {
            float4 v4 = src[i];
            const int d = seg * 16 + i * 4;
            Qt[d + 0][row] = v4.x;
            Qt[d + 1][row] = v4.y;
            Qt[d + 2][row] = v4.z;
            Qt[d + 3][row] = v4.w;
        }
    }

    float mq[4];
#pragma unroll
    for (int i = 0; i < 4; i++)
        mq[i] = mrow[q0 + tr * 4 + i] ? 0.0f : -1e9f;

    float m_i[4], l_i[4], acc[4][4];
#pragma unroll
    for (int i = 0; i < 4; i++) {
        m_i[i] = -3.0e38f;
        l_i[i] = 0.0f;
#pragma unroll
        for (int j = 0; j < 4; j++) acc[i][j] = 0.0f;
    }

    __syncthreads();

    for (int k0 = 0; k0 < SS; k0 += 64) {
        // load K tile (transposed, d-major) + V tile (k-major) + key mask
        {
            const int row = tid >> 2, seg = tid & 3;
            const float4* ksrc = reinterpret_cast<const float4*>(
                &Kb[(size_t)(k0 + row) * 64 + seg * 16]);
            const float4* vsrc = reinterpret_cast<const float4*>(
                &Vb[(size_t)(k0 + row) * 64 + seg * 16]);
#pragma unroll
            for (int i = 0; i < 4; i++) {
                const int d = seg * 16 + i * 4;
                float4 kv = ksrc[i];
                Kt[d + 0][row] = kv.x;
                Kt[d + 1][row] = kv.y;
                Kt[d + 2][row] = kv.z;
                Kt[d + 3][row] = kv.w;
                float4 vv = vsrc[i];
                *reinterpret_cast<float4*>(&Vs[row][d]) = vv;
            }
            if (tid < 64) Mk[tid] = mrow[k0 + tid] ? 0.0f : -1e9f;
        }
        __syncthreads();

        // scores: 4x4 micro-tile over Qt/Kt (both d-major)
        float s[4][4];
#pragma unroll
        for (int i = 0; i < 4; i++)
#pragma unroll
            for (int j = 0; j < 4; j++) s[i][j] = 0.0f;
#pragma unroll 8
        for (int d = 0; d < 64; d++) {
            float4 av = *reinterpret_cast<const float4*>(&Qt[d][tr * 4]);
            float4 bv = *reinterpret_cast<const float4*>(&Kt[d][tc * 4]);
            float a[4] = {av.x, av.y, av.z, av.w};
            float kk[4] = {bv.x, bv.y, bv.z, bv.w};
#pragma unroll
            for (int i = 0; i < 4; i++)
#pragma unroll
                for (int j = 0; j < 4; j++) s[i][j] += a[i] * kk[j];
        }
        float mkv[4];
#pragma unroll
        for (int j = 0; j < 4; j++) mkv[j] = Mk[tc * 4 + j];
#pragma unroll
        for (int i = 0; i < 4; i++)
#pragma unroll
            for (int j = 0; j < 4; j++)
                s[i][j] = (s[i][j] * 0.125f + mkv[j]) + mq[i];  // fp32 absorption as in ref

        // online softmax (row state replicated across the 16-lane col group)
        float p[4][4];
#pragma unroll
        for (int i = 0; i < 4; i++) {
            float tm = fmaxf(fmaxf(s[i][0], s[i][1]), fmaxf(s[i][2], s[i][3]));
#pragma unroll
            for (int off = 1; off < 16; off <<= 1)
                tm = fmaxf(tm, __shfl_xor_sync(0xffffffffu, tm, off));
            const float mn = fmaxf(m_i[i], tm);
            const float scale = __expf(m_i[i] - mn);
            float rs = 0.0f;
#pragma unroll
            for (int j = 0; j < 4; j++) {
                p[i][j] = __expf(s[i][j] - mn);
                rs += p[i][j];
            }
#pragma unroll
            for (int off = 1; off < 16; off <<= 1)
                rs += __shfl_xor_sync(0xffffffffu, rs, off);
            l_i[i] = l_i[i] * scale + rs;
            m_i[i] = mn;
#pragma unroll
            for (int j = 0; j < 4; j++) acc[i][j] *= scale;
        }
        // store P tile (r-major, float4, conflict-free)
#pragma unroll
        for (int i = 0; i < 4; i++) {
            float4 pv = make_float4(p[i][0], p[i][1], p[i][2], p[i][3]);
            *reinterpret_cast<float4*>(&Ps[tr * 4 + i][tc * 4]) = pv;
        }
        __syncthreads();

        // PV: acc[i][j] += sum_k Ps[r][k] * Vs[k][d]
#pragma unroll 4
        for (int k = 0; k < 64; k++) {
            float4 v4 = *reinterpret_cast<const float4*>(&Vs[k][tc * 4]);
            float vb[4] = {v4.x, v4.y, v4.z, v4.w};
            float pa[4];
#pragma unroll
            for (int i = 0; i < 4; i++) pa[i] = Ps[tr * 4 + i][k];
#pragma unroll
            for (int i = 0; i < 4; i++)
#pragma unroll
                for (int j = 0; j < 4; j++) acc[i][j] += pa[i] * vb[j];
        }
        __syncthreads();
    }

    // epilogue: normalize + write ctx in (B,S,H*64) layout
#pragma unroll
    for (int i = 0; i < 4; i++) {
        const float inv = 1.0f / l_i[i];
        const int q = q0 + tr * 4 + i;
        float4 o = make_float4(acc[i][0] * inv, acc[i][1] * inv,
                               acc[i][2] * inv, acc[i][3] * inv);
        *reinterpret_cast<float4*>(
            &ctx[((size_t)(b * SS + q)) * 512 + h * 64 + tc * 4]) = o;
    }
}

// ---------------- launch ----------------
extern "C" void kernel_launch(void* const* d_in, const int* in_sizes, int n_in,
                              void* d_out, int out_size)
{
    (void)in_sizes; (void)n_in; (void)out_size;
    const float* query = (const float*)d_in[0];
    const float* value = (const float*)d_in[1];
    const int*   amask = (const int*)d_in[2];
    const float* Wq = (const float*)d_in[3];
    const float* bq = (const float*)d_in[4];
    const float* Wk = (const float*)d_in[5];
    const float* bk = (const float*)d_in[6];
    const float* Wv = (const float*)d_in[7];
    const float* bv = (const float*)d_in[8];
    const float* Wo = (const float*)d_in[9];
    const float* bo = (const float*)d_in[10];
    float* out = (float*)d_out;

    float *pq, *pk, *pv, *pctx;
    cudaGetSymbolAddress((void**)&pq, g_q);
    cudaGetSymbolAddress((void**)&pk, g_k);
    cudaGetSymbolAddress((void**)&pv, g_v);
    cudaGetSymbolAddress((void**)&pctx, g_ctx);

    const int M = BB * SS;           // 8192
    const dim3 ggrid(DD / 64, M / 64);  // (8,128)

    // QKV projections into split-head layout
    gemm_kernel<true><<<ggrid, 256>>>(query, Wq, bq, pq, M, DD, HH * DH);
    gemm_kernel<true><<<ggrid, 256>>>(value, Wk, bk, pk, M, DD, HH * DH);
    gemm_kernel<true><<<ggrid, 256>>>(value, Wv, bv, pv, M, DD, HH * DH);

    // attention
    const int smem = (4 * 64 * 68 + 64) * sizeof(float);  // ~69.9 KB
    cudaFuncSetAttribute(attn_kernel, cudaFuncAttributeMaxDynamicSharedMemorySize, smem);
    attn_kernel<<<dim3(SS / 64, BB * HH), 256, smem>>>(pq, pk, pv, amask, pctx);

    // output projection
    gemm_kernel<false><<<ggrid, 256>>>(pctx, Wo, bo, out, M, HH * DH, DD);
}